// round 1
// baseline (speedup 1.0000x reference)
#include <cuda_runtime.h>
#include <cstdint>

// Problem constants (GB300 bench shapes)
#define DD     64
#define NP_MAX 100000
#define NG_MAX 40000

// ---------------- static scratch (no runtime allocation allowed) -------------
__device__ float g_xp[2][NP_MAX * DD];   // ping-pong protein features
__device__ float g_xg[2][NG_MAX * DD];   // ping-pong go features
__device__ float g_agg_p[NP_MAX * DD];
__device__ float g_agg_g[NG_MAX * DD];
__device__ int   g_cnt_p[NP_MAX];
__device__ int   g_cnt_g[NG_MAX];
__device__ float g_inv_p[NP_MAX];
__device__ float g_inv_g[NG_MAX];

// ---------------- small utility kernels --------------------------------------
__global__ void zero_f_kernel(float* p, long long n) {
    long long i = (long long)blockIdx.x * blockDim.x + threadIdx.x;
    long long stride = (long long)gridDim.x * blockDim.x;
    for (; i < n; i += stride) p[i] = 0.0f;
}

__global__ void zero_i_kernel(int* p, int n) {
    int i = blockIdx.x * blockDim.x + threadIdx.x;
    if (i < n) p[i] = 0;
}

__global__ void hist_kernel(const int* __restrict__ dst, int E, int* __restrict__ cnt) {
    int i = blockIdx.x * blockDim.x + threadIdx.x;
    if (i < E) atomicAdd(&cnt[dst[i]], 1);
}

__global__ void inv_kernel(const int* __restrict__ cnt, float* __restrict__ inv, int n) {
    int i = blockIdx.x * blockDim.x + threadIdx.x;
    if (i < n) inv[i] = 1.0f / (float)max(cnt[i], 1);
}

// xp0[i,:] = protein_emb[nid[i],:]
__global__ void init_xp_kernel(const float* __restrict__ pe, const int* __restrict__ nid,
                               float* __restrict__ out, int np) {
    long long idx = (long long)blockIdx.x * blockDim.x + threadIdx.x;
    long long n = (long long)np * DD;
    if (idx >= n) return;
    int r = (int)(idx >> 6);
    int c = (int)(idx & 63);
    out[idx] = pe[(long long)nid[r] * DD + c];
}

// ---------------- xg init GEMM: [M,K] @ [K,64] + bias + emb[nid] -------------
#define GBK 8
__global__ void gemm_xg_kernel(const float* __restrict__ A, const float* __restrict__ W,
                               const float* __restrict__ bias, const float* __restrict__ emb,
                               const int* __restrict__ nid, float* __restrict__ out,
                               int M, int K) {
    __shared__ float As[GBK][68];   // As[k][row], padded for bank spread, 16B-aligned rows
    __shared__ float Bs[GBK][68];   // Bs[k][col]
    int tid = threadIdx.x;          // 256 threads
    int tx = tid & 15;              // output col group (4 cols)
    int ty = tid >> 4;              // output row group (4 rows)
    int rowBase = blockIdx.x * 64;

    float acc[4][4];
#pragma unroll
    for (int i = 0; i < 4; i++)
#pragma unroll
        for (int j = 0; j < 4; j++) acc[i][j] = 0.0f;

    int la_row = tid >> 2;          // 0..63
    int la_k   = (tid & 3) * 2;     // 0,2,4,6
    int lb_k   = tid >> 5;          // 0..7
    int lb_c   = (tid & 31) * 2;    // 0..62

    const float* Arow = A + (long long)(rowBase + la_row) * K;
    bool a_ok = (rowBase + la_row) < M;

    for (int k0 = 0; k0 < K; k0 += GBK) {
        float a0 = 0.f, a1 = 0.f;
        if (a_ok) { a0 = Arow[k0 + la_k]; a1 = Arow[k0 + la_k + 1]; }
        As[la_k][la_row] = a0;
        As[la_k + 1][la_row] = a1;
        Bs[lb_k][lb_c]     = W[(long long)(k0 + lb_k) * 64 + lb_c];
        Bs[lb_k][lb_c + 1] = W[(long long)(k0 + lb_k) * 64 + lb_c + 1];
        __syncthreads();
#pragma unroll
        for (int k = 0; k < GBK; k++) {
            float4 av = *(const float4*)&As[k][ty * 4];
            float4 bv = *(const float4*)&Bs[k][tx * 4];
            acc[0][0] += av.x * bv.x; acc[0][1] += av.x * bv.y; acc[0][2] += av.x * bv.z; acc[0][3] += av.x * bv.w;
            acc[1][0] += av.y * bv.x; acc[1][1] += av.y * bv.y; acc[1][2] += av.y * bv.z; acc[1][3] += av.y * bv.w;
            acc[2][0] += av.z * bv.x; acc[2][1] += av.z * bv.y; acc[2][2] += av.z * bv.z; acc[2][3] += av.z * bv.w;
            acc[3][0] += av.w * bv.x; acc[3][1] += av.w * bv.y; acc[3][2] += av.w * bv.z; acc[3][3] += av.w * bv.w;
        }
        __syncthreads();
    }

#pragma unroll
    for (int i = 0; i < 4; i++) {
        int r = rowBase + ty * 4 + i;
        if (r >= M) continue;
        int g = nid[r];
#pragma unroll
        for (int j = 0; j < 4; j++) {
            int c = tx * 4 + j;
            out[(long long)r * 64 + c] = acc[i][j] + bias[c] + emb[(long long)g * 64 + c];
        }
    }
}

// ---------------- edge scatter: agg[dst,:] += x[src,:]  (16 threads / edge) --
__global__ void scatter_kernel(const float* __restrict__ xsrc, float* __restrict__ agg,
                               const int* __restrict__ src, const int* __restrict__ dst,
                               int E) {
    long long idx = (long long)blockIdx.x * blockDim.x + threadIdx.x;
    long long total = (long long)E * 16;
    if (idx >= total) return;
    int e = (int)(idx >> 4);
    int j = (int)(idx & 15);
    int s = __ldg(&src[e]);
    int d = __ldg(&dst[e]);
    float4 v = __ldg((const float4*)(xsrc + (long long)s * DD) + j);
    float* p = agg + (long long)d * DD + (long long)j * 4;
    asm volatile("red.global.add.v4.f32 [%0], {%1, %2, %3, %4};"
                 :: "l"(p), "f"(v.x), "f"(v.y), "f"(v.z), "f"(v.w)
                 : "memory");
}

// ------- node update: out = (agg*inv) @ Wl + bl + x @ Wr, optional relu ------
__global__ void update_kernel(const float* __restrict__ agg, const float* __restrict__ inv,
                              const float* __restrict__ x,
                              const float* __restrict__ Wl, const float* __restrict__ bl,
                              const float* __restrict__ Wr,
                              float* __restrict__ out, int n, int do_relu) {
    __shared__ float sWl[64 * 64];
    __shared__ float sWr[64 * 64];
    for (int i = threadIdx.x; i < 64 * 64; i += blockDim.x) {
        sWl[i] = Wl[i];
        sWr[i] = Wr[i];
    }
    __syncthreads();

    int warp = threadIdx.x >> 5;
    int lane = threadIdx.x & 31;
    int rowsPerBlock = blockDim.x >> 5;

    for (int row = blockIdx.x * rowsPerBlock + warp; row < n;
         row += gridDim.x * rowsPerBlock) {
        float ic = inv[row];
        long long base = (long long)row * 64;
        float a0 = agg[base + lane] * ic;
        float a1 = agg[base + 32 + lane] * ic;
        float x0 = x[base + lane];
        float x1 = x[base + 32 + lane];
        float acc0 = bl[lane];
        float acc1 = bl[32 + lane];
#pragma unroll
        for (int k = 0; k < 32; k++) {
            float av = __shfl_sync(0xffffffffu, a0, k);
            float xv = __shfl_sync(0xffffffffu, x0, k);
            acc0 += av * sWl[k * 64 + lane]      + xv * sWr[k * 64 + lane];
            acc1 += av * sWl[k * 64 + 32 + lane] + xv * sWr[k * 64 + 32 + lane];
        }
#pragma unroll
        for (int k = 0; k < 32; k++) {
            float av = __shfl_sync(0xffffffffu, a1, k);
            float xv = __shfl_sync(0xffffffffu, x1, k);
            acc0 += av * sWl[(32 + k) * 64 + lane]      + xv * sWr[(32 + k) * 64 + lane];
            acc1 += av * sWl[(32 + k) * 64 + 32 + lane] + xv * sWr[(32 + k) * 64 + 32 + lane];
        }
        if (do_relu) { acc0 = fmaxf(acc0, 0.0f); acc1 = fmaxf(acc1, 0.0f); }
        out[base + lane] = acc0;
        out[base + 32 + lane] = acc1;
    }
}

// ---------------- classifier: out[e] = dot(xp[ls[e]], xg[ld[e]]) (8 thr/edge)
__global__ void classify_kernel(const float* __restrict__ xp, const float* __restrict__ xg,
                                const int* __restrict__ ls, const int* __restrict__ ld,
                                float* __restrict__ out, int E) {
    long long idx = (long long)blockIdx.x * blockDim.x + threadIdx.x;
    long long total = (long long)E * 8;
    if (idx >= total) return;
    int e = (int)(idx >> 3);
    int j = (int)(idx & 7);
    int a = __ldg(&ls[e]);
    int b = __ldg(&ld[e]);
    const float4* pa = (const float4*)(xp + (long long)a * DD);
    const float4* pb = (const float4*)(xg + (long long)b * DD);
    float4 u0 = __ldg(pa + j * 2);
    float4 u1 = __ldg(pa + j * 2 + 1);
    float4 v0 = __ldg(pb + j * 2);
    float4 v1 = __ldg(pb + j * 2 + 1);
    float s = u0.x * v0.x + u0.y * v0.y + u0.z * v0.z + u0.w * v0.w
            + u1.x * v1.x + u1.y * v1.y + u1.z * v1.z + u1.w * v1.w;
    // reduce over 8-lane group (xor offsets stay within the group)
    s += __shfl_xor_sync(0xffffffffu, s, 4);
    s += __shfl_xor_sync(0xffffffffu, s, 2);
    s += __shfl_xor_sync(0xffffffffu, s, 1);
    if (j == 0) out[e] = s;
}

// ---------------- host driver ------------------------------------------------
static inline int cdiv(long long a, int b) { return (int)((a + b - 1) / b); }

extern "C" void kernel_launch(void* const* d_in, const int* in_sizes, int n_in,
                              void* d_out, int out_size) {
    const float* go_x        = (const float*)d_in[0];
    const float* protein_emb = (const float*)d_in[1];
    const float* go_emb      = (const float*)d_in[2];
    const float* lin_W       = (const float*)d_in[3];
    const float* lin_b       = (const float*)d_in[4];
    const float* Wl          = (const float*)d_in[5];
    const float* bl          = (const float*)d_in[6];
    const float* Wr          = (const float*)d_in[7];
    const int*   protein_nid = (const int*)d_in[8];
    const int*   go_nid      = (const int*)d_in[9];
    const int*   src_pg      = (const int*)d_in[10];
    const int*   dst_pg      = (const int*)d_in[11];
    const int*   src_gp      = (const int*)d_in[12];
    const int*   dst_gp      = (const int*)d_in[13];
    const int*   label_src   = (const int*)d_in[14];
    const int*   label_dst   = (const int*)d_in[15];

    int NP = in_sizes[8];
    int NG = in_sizes[9];
    int E  = in_sizes[10];
    int EL = in_sizes[14];
    int K  = (int)((long long)in_sizes[0] / NG);          // F_GO = 1000
    int L  = (int)((long long)in_sizes[5] / (2 * 64 * 64)); // 3

    float *xp_buf, *xg_buf, *agg_p, *agg_g, *inv_p, *inv_g;
    int *cnt_p, *cnt_g;
    cudaGetSymbolAddress((void**)&xp_buf, g_xp);
    cudaGetSymbolAddress((void**)&xg_buf, g_xg);
    cudaGetSymbolAddress((void**)&agg_p, g_agg_p);
    cudaGetSymbolAddress((void**)&agg_g, g_agg_g);
    cudaGetSymbolAddress((void**)&cnt_p, g_cnt_p);
    cudaGetSymbolAddress((void**)&cnt_g, g_cnt_g);
    cudaGetSymbolAddress((void**)&inv_p, g_inv_p);
    cudaGetSymbolAddress((void**)&inv_g, g_inv_g);

    float* xp[2] = { xp_buf, xp_buf + (long long)NP_MAX * DD };
    float* xg[2] = { xg_buf, xg_buf + (long long)NG_MAX * DD };

    const int TB = 256;

    // degree counts + inverses (shared by all layers)
    zero_i_kernel<<<cdiv(NG, TB), TB>>>(cnt_g, NG);
    zero_i_kernel<<<cdiv(NP, TB), TB>>>(cnt_p, NP);
    hist_kernel<<<cdiv(E, TB), TB>>>(dst_pg, E, cnt_g);
    hist_kernel<<<cdiv(E, TB), TB>>>(dst_gp, E, cnt_p);
    inv_kernel<<<cdiv(NG, TB), TB>>>(cnt_g, inv_g, NG);
    inv_kernel<<<cdiv(NP, TB), TB>>>(cnt_p, inv_p, NP);

    // input embeddings
    init_xp_kernel<<<cdiv((long long)NP * DD, TB), TB>>>(protein_emb, protein_nid, xp[0], NP);
    gemm_xg_kernel<<<cdiv(NG, 64), 256>>>(go_x, lin_W, lin_b, go_emb, go_nid, xg[0], NG, K);

    int cur = 0;
    for (int l = 0; l < L; l++) {
        int nxt = cur ^ 1;
        zero_f_kernel<<<2048, TB>>>(agg_g, (long long)NG * DD);
        zero_f_kernel<<<2048, TB>>>(agg_p, (long long)NP * DD);
        scatter_kernel<<<cdiv((long long)E * 16, TB), TB>>>(xp[cur], agg_g, src_pg, dst_pg, E);
        scatter_kernel<<<cdiv((long long)E * 16, TB), TB>>>(xg[cur], agg_p, src_gp, dst_gp, E);
        int relu = (l < L - 1) ? 1 : 0;
        update_kernel<<<592, 256>>>(agg_g, inv_g, xg[cur],
                                    Wl + (long long)(l * 2 + 0) * 64 * 64,
                                    bl + (long long)(l * 2 + 0) * 64,
                                    Wr + (long long)(l * 2 + 0) * 64 * 64,
                                    xg[nxt], NG, relu);
        update_kernel<<<592, 256>>>(agg_p, inv_p, xp[cur],
                                    Wl + (long long)(l * 2 + 1) * 64 * 64,
                                    bl + (long long)(l * 2 + 1) * 64,
                                    Wr + (long long)(l * 2 + 1) * 64 * 64,
                                    xp[nxt], NP, relu);
        cur = nxt;
    }

    classify_kernel<<<cdiv((long long)EL * 8, TB), TB>>>(xp[cur], xg[cur],
                                                         label_src, label_dst,
                                                         (float*)d_out, EL);
}

// round 3
// speedup vs baseline: 1.7902x; 1.7902x over previous
#include <cuda_runtime.h>
#include <cstdint>

// Problem constants (GB300 bench shapes)
#define DD     64
#define NP_MAX 100000
#define NG_MAX 40000
#define E_MAX  1600000

// ---------------- static scratch (no runtime allocation allowed) -------------
__device__ float g_xp[2][NP_MAX * DD];   // ping-pong protein features
__device__ float g_xg[2][NG_MAX * DD];   // ping-pong go features
__device__ int   g_cnt_p[NP_MAX];
__device__ int   g_cnt_g[NG_MAX];
__device__ int   g_off_g[NG_MAX + 1];    // CSR row offsets (dst = go)
__device__ int   g_off_p[NP_MAX + 1];    // CSR row offsets (dst = protein)
__device__ int   g_cur_g[NG_MAX];        // fill cursors
__device__ int   g_cur_p[NP_MAX];
__device__ int   g_csr_pg[E_MAX];        // src protein ids sorted by go dst
__device__ int   g_csr_gp[E_MAX];        // src go ids sorted by protein dst

// ---------------- small utility kernels --------------------------------------
__global__ void zero_i_kernel(int* p, int n) {
    int i = blockIdx.x * blockDim.x + threadIdx.x;
    if (i < n) p[i] = 0;
}

__global__ void hist_kernel(const int* __restrict__ dst, int E, int* __restrict__ cnt) {
    int i = blockIdx.x * blockDim.x + threadIdx.x;
    if (i < E) atomicAdd(&cnt[dst[i]], 1);
}

// single-block exclusive scan: off[i] = sum(cnt[0..i)), off[n] = total,
// cursor[i] initialized to off[i]
__global__ void scan_kernel(const int* __restrict__ cnt, int* __restrict__ off,
                            int* __restrict__ cursor, int n) {
    __shared__ int warp_sums[32];
    __shared__ int s_carry;
    int tid = threadIdx.x;           // 1024 threads
    int lane = tid & 31, warp = tid >> 5;
    if (tid == 0) s_carry = 0;
    __syncthreads();
    for (int base = 0; base < n; base += 1024) {
        int i = base + tid;
        int v = (i < n) ? cnt[i] : 0;
        int x = v;
#pragma unroll
        for (int o = 1; o < 32; o <<= 1) {
            int y = __shfl_up_sync(0xffffffffu, x, o);
            if (lane >= o) x += y;
        }
        if (lane == 31) warp_sums[warp] = x;
        __syncthreads();
        if (warp == 0) {
            int w = warp_sums[lane];
#pragma unroll
            for (int o = 1; o < 32; o <<= 1) {
                int y = __shfl_up_sync(0xffffffffu, w, o);
                if (lane >= o) w += y;
            }
            warp_sums[lane] = w;
        }
        __syncthreads();
        int excl = x - v + (warp > 0 ? warp_sums[warp - 1] : 0) + s_carry;
        if (i < n) { off[i] = excl; cursor[i] = excl; }
        __syncthreads();
        if (tid == 0) s_carry += warp_sums[31];
        __syncthreads();
    }
    if (tid == 0) off[n] = s_carry;
}

// fill CSR: csr[pos] = src[e], pos allocated via per-row cursor
__global__ void fill_kernel(const int* __restrict__ src, const int* __restrict__ dst,
                            int* __restrict__ cursor, int* __restrict__ csr, int E) {
    int i = blockIdx.x * blockDim.x + threadIdx.x;
    if (i < E) {
        int d = dst[i];
        int pos = atomicAdd(&cursor[d], 1);
        csr[pos] = src[i];
    }
}

// xp0[i,:] = protein_emb[nid[i],:]
__global__ void init_xp_kernel(const float* __restrict__ pe, const int* __restrict__ nid,
                               float* __restrict__ out, int np) {
    long long idx = (long long)blockIdx.x * blockDim.x + threadIdx.x;
    long long n = (long long)np * DD;
    if (idx >= n) return;
    int r = (int)(idx >> 6);
    int c = (int)(idx & 63);
    out[idx] = pe[(long long)nid[r] * DD + c];
}

// ---------------- xg init GEMM: [M,K] @ [K,64] + bias + emb[nid] -------------
#define GBK 8
__global__ void gemm_xg_kernel(const float* __restrict__ A, const float* __restrict__ W,
                               const float* __restrict__ bias, const float* __restrict__ emb,
                               const int* __restrict__ nid, float* __restrict__ out,
                               int M, int K) {
    __shared__ float As[GBK][68];
    __shared__ float Bs[GBK][68];
    int tid = threadIdx.x;          // 256 threads
    int tx = tid & 15;
    int ty = tid >> 4;
    int rowBase = blockIdx.x * 64;

    float acc[4][4];
#pragma unroll
    for (int i = 0; i < 4; i++)
#pragma unroll
        for (int j = 0; j < 4; j++) acc[i][j] = 0.0f;

    int la_row = tid >> 2;
    int la_k   = (tid & 3) * 2;
    int lb_k   = tid >> 5;
    int lb_c   = (tid & 31) * 2;

    const float* Arow = A + (long long)(rowBase + la_row) * K;
    bool a_ok = (rowBase + la_row) < M;

    for (int k0 = 0; k0 < K; k0 += GBK) {
        float a0 = 0.f, a1 = 0.f;
        if (a_ok) { a0 = Arow[k0 + la_k]; a1 = Arow[k0 + la_k + 1]; }
        As[la_k][la_row] = a0;
        As[la_k + 1][la_row] = a1;
        Bs[lb_k][lb_c]     = W[(long long)(k0 + lb_k) * 64 + lb_c];
        Bs[lb_k][lb_c + 1] = W[(long long)(k0 + lb_k) * 64 + lb_c + 1];
        __syncthreads();
#pragma unroll
        for (int k = 0; k < GBK; k++) {
            float4 av = *(const float4*)&As[k][ty * 4];
            float4 bv = *(const float4*)&Bs[k][tx * 4];
            acc[0][0] += av.x * bv.x; acc[0][1] += av.x * bv.y; acc[0][2] += av.x * bv.z; acc[0][3] += av.x * bv.w;
            acc[1][0] += av.y * bv.x; acc[1][1] += av.y * bv.y; acc[1][2] += av.y * bv.z; acc[1][3] += av.y * bv.w;
            acc[2][0] += av.z * bv.x; acc[2][1] += av.z * bv.y; acc[2][2] += av.z * bv.z; acc[2][3] += av.z * bv.w;
            acc[3][0] += av.w * bv.x; acc[3][1] += av.w * bv.y; acc[3][2] += av.w * bv.z; acc[3][3] += av.w * bv.w;
        }
        __syncthreads();
    }

#pragma unroll
    for (int i = 0; i < 4; i++) {
        int r = rowBase + ty * 4 + i;
        if (r >= M) continue;
        int g = nid[r];
#pragma unroll
        for (int j = 0; j < 4; j++) {
            int c = tx * 4 + j;
            out[(long long)r * 64 + c] = acc[i][j] + bias[c] + emb[(long long)g * 64 + c];
        }
    }
}

// --------- fused mean-aggregate + node update -------------------------------
// out[r,:] = relu?( (mean_{s in csr row r} xsrc[s,:]) @ Wl + bl + xdst[r,:] @ Wr )
// one warp per dst row; lane holds cols (lane, lane+32)
__global__ void __launch_bounds__(512, 3) agg_update_kernel(
    const float* __restrict__ xsrc, const float* __restrict__ xdst,
    const int* __restrict__ off, const int* __restrict__ csr,
    const float* __restrict__ Wl, const float* __restrict__ bl,
    const float* __restrict__ Wr,
    float* __restrict__ out, int n, int do_relu) {
    __shared__ float sWl[64 * 64];
    __shared__ float sWr[64 * 64];
    for (int i = threadIdx.x; i < 64 * 64; i += blockDim.x) {
        sWl[i] = Wl[i];
        sWr[i] = Wr[i];
    }
    __syncthreads();

    int warp = threadIdx.x >> 5;
    int lane = threadIdx.x & 31;
    int wpb = blockDim.x >> 5;

    for (int row = blockIdx.x * wpb + warp; row < n; row += gridDim.x * wpb) {
        int e0 = __ldg(&off[row]);
        int e1 = __ldg(&off[row + 1]);
        float a0 = 0.0f, a1 = 0.0f;
        int e = e0;
        for (; e + 4 <= e1; e += 4) {
            int s0 = __ldg(&csr[e]);
            int s1 = __ldg(&csr[e + 1]);
            int s2 = __ldg(&csr[e + 2]);
            int s3 = __ldg(&csr[e + 3]);
            const float* p0 = xsrc + (long long)s0 * DD;
            const float* p1 = xsrc + (long long)s1 * DD;
            const float* p2 = xsrc + (long long)s2 * DD;
            const float* p3 = xsrc + (long long)s3 * DD;
            float v00 = __ldg(p0 + lane),      v01 = __ldg(p0 + 32 + lane);
            float v10 = __ldg(p1 + lane),      v11 = __ldg(p1 + 32 + lane);
            float v20 = __ldg(p2 + lane),      v21 = __ldg(p2 + 32 + lane);
            float v30 = __ldg(p3 + lane),      v31 = __ldg(p3 + 32 + lane);
            a0 += (v00 + v10) + (v20 + v30);
            a1 += (v01 + v11) + (v21 + v31);
        }
        for (; e < e1; e++) {
            int s = __ldg(&csr[e]);
            const float* p = xsrc + (long long)s * DD;
            a0 += __ldg(p + lane);
            a1 += __ldg(p + 32 + lane);
        }
        float ic = 1.0f / (float)max(e1 - e0, 1);
        a0 *= ic; a1 *= ic;

        long long base = (long long)row * DD;
        float x0 = __ldg(&xdst[base + lane]);
        float x1 = __ldg(&xdst[base + 32 + lane]);
        float acc0 = bl[lane];
        float acc1 = bl[32 + lane];
#pragma unroll
        for (int k = 0; k < 32; k++) {
            float av = __shfl_sync(0xffffffffu, a0, k);
            float xv = __shfl_sync(0xffffffffu, x0, k);
            acc0 += av * sWl[k * 64 + lane]      + xv * sWr[k * 64 + lane];
            acc1 += av * sWl[k * 64 + 32 + lane] + xv * sWr[k * 64 + 32 + lane];
        }
#pragma unroll
        for (int k = 0; k < 32; k++) {
            float av = __shfl_sync(0xffffffffu, a1, k);
            float xv = __shfl_sync(0xffffffffu, x1, k);
            acc0 += av * sWl[(32 + k) * 64 + lane]      + xv * sWr[(32 + k) * 64 + lane];
            acc1 += av * sWl[(32 + k) * 64 + 32 + lane] + xv * sWr[(32 + k) * 64 + 32 + lane];
        }
        if (do_relu) { acc0 = fmaxf(acc0, 0.0f); acc1 = fmaxf(acc1, 0.0f); }
        out[base + lane] = acc0;
        out[base + 32 + lane] = acc1;
    }
}

// ---------------- classifier: out[e] = dot(xp[ls[e]], xg[ld[e]]) (8 thr/edge)
__global__ void classify_kernel(const float* __restrict__ xp, const float* __restrict__ xg,
                                const int* __restrict__ ls, const int* __restrict__ ld,
                                float* __restrict__ out, int E) {
    long long idx = (long long)blockIdx.x * blockDim.x + threadIdx.x;
    long long total = (long long)E * 8;
    if (idx >= total) return;
    int e = (int)(idx >> 3);
    int j = (int)(idx & 7);
    int a = __ldg(&ls[e]);
    int b = __ldg(&ld[e]);
    const float4* pa = (const float4*)(xp + (long long)a * DD);
    const float4* pb = (const float4*)(xg + (long long)b * DD);
    float4 u0 = __ldg(pa + j * 2);
    float4 u1 = __ldg(pa + j * 2 + 1);
    float4 v0 = __ldg(pb + j * 2);
    float4 v1 = __ldg(pb + j * 2 + 1);
    float s = u0.x * v0.x + u0.y * v0.y + u0.z * v0.z + u0.w * v0.w
            + u1.x * v1.x + u1.y * v1.y + u1.z * v1.z + u1.w * v1.w;
    s += __shfl_xor_sync(0xffffffffu, s, 4);
    s += __shfl_xor_sync(0xffffffffu, s, 2);
    s += __shfl_xor_sync(0xffffffffu, s, 1);
    if (j == 0) out[e] = s;
}

// ---------------- host driver ------------------------------------------------
static inline int cdiv(long long a, int b) { return (int)((a + b - 1) / b); }

extern "C" void kernel_launch(void* const* d_in, const int* in_sizes, int n_in,
                              void* d_out, int out_size) {
    const float* go_x        = (const float*)d_in[0];
    const float* protein_emb = (const float*)d_in[1];
    const float* go_emb      = (const float*)d_in[2];
    const float* lin_W       = (const float*)d_in[3];
    const float* lin_b       = (const float*)d_in[4];
    const float* Wl          = (const float*)d_in[5];
    const float* bl          = (const float*)d_in[6];
    const float* Wr          = (const float*)d_in[7];
    const int*   protein_nid = (const int*)d_in[8];
    const int*   go_nid      = (const int*)d_in[9];
    const int*   src_pg      = (const int*)d_in[10];
    const int*   dst_pg      = (const int*)d_in[11];
    const int*   src_gp      = (const int*)d_in[12];
    const int*   dst_gp      = (const int*)d_in[13];
    const int*   label_src   = (const int*)d_in[14];
    const int*   label_dst   = (const int*)d_in[15];

    int NP = in_sizes[8];
    int NG = in_sizes[9];
    int E  = in_sizes[10];
    int EL = in_sizes[14];
    int K  = (int)((long long)in_sizes[0] / NG);
    int L  = (int)((long long)in_sizes[5] / (2 * 64 * 64));

    float *xp_buf, *xg_buf;
    int *cnt_p, *cnt_g, *off_g, *off_p, *cur_g, *cur_p, *csr_pg, *csr_gp;
    cudaGetSymbolAddress((void**)&xp_buf, g_xp);
    cudaGetSymbolAddress((void**)&xg_buf, g_xg);
    cudaGetSymbolAddress((void**)&cnt_p, g_cnt_p);
    cudaGetSymbolAddress((void**)&cnt_g, g_cnt_g);
    cudaGetSymbolAddress((void**)&off_g, g_off_g);
    cudaGetSymbolAddress((void**)&off_p, g_off_p);
    cudaGetSymbolAddress((void**)&cur_g, g_cur_g);
    cudaGetSymbolAddress((void**)&cur_p, g_cur_p);
    cudaGetSymbolAddress((void**)&csr_pg, g_csr_pg);
    cudaGetSymbolAddress((void**)&csr_gp, g_csr_gp);

    float* xp[2] = { xp_buf, xp_buf + (long long)NP_MAX * DD };
    float* xg[2] = { xg_buf, xg_buf + (long long)NG_MAX * DD };

    const int TB = 256;

    // ---- CSR build (reused by all layers) ----
    zero_i_kernel<<<cdiv(NG, TB), TB>>>(cnt_g, NG);
    zero_i_kernel<<<cdiv(NP, TB), TB>>>(cnt_p, NP);
    hist_kernel<<<cdiv(E, TB), TB>>>(dst_pg, E, cnt_g);
    hist_kernel<<<cdiv(E, TB), TB>>>(dst_gp, E, cnt_p);
    scan_kernel<<<1, 1024>>>(cnt_g, off_g, cur_g, NG);
    scan_kernel<<<1, 1024>>>(cnt_p, off_p, cur_p, NP);
    fill_kernel<<<cdiv(E, TB), TB>>>(src_pg, dst_pg, cur_g, csr_pg, E);
    fill_kernel<<<cdiv(E, TB), TB>>>(src_gp, dst_gp, cur_p, csr_gp, E);

    // ---- input embeddings ----
    init_xp_kernel<<<cdiv((long long)NP * DD, TB), TB>>>(protein_emb, protein_nid, xp[0], NP);
    gemm_xg_kernel<<<cdiv(NG, 64), 256>>>(go_x, lin_W, lin_b, go_emb, go_nid, xg[0], NG, K);

    // ---- layers ----
    int cur = 0;
    for (int l = 0; l < L; l++) {
        int nxt = cur ^ 1;
        int relu = (l < L - 1) ? 1 : 0;
        // go update: aggregate proteins -> go
        agg_update_kernel<<<592, 512>>>(xp[cur], xg[cur], off_g, csr_pg,
                                        Wl + (long long)(l * 2 + 0) * 64 * 64,
                                        bl + (long long)(l * 2 + 0) * 64,
                                        Wr + (long long)(l * 2 + 0) * 64 * 64,
                                        xg[nxt], NG, relu);
        // protein update: aggregate go -> protein
        agg_update_kernel<<<592, 512>>>(xg[cur], xp[cur], off_p, csr_gp,
                                        Wl + (long long)(l * 2 + 1) * 64 * 64,
                                        bl + (long long)(l * 2 + 1) * 64,
                                        Wr + (long long)(l * 2 + 1) * 64 * 64,
                                        xp[nxt], NP, relu);
        cur = nxt;
    }

    classify_kernel<<<cdiv((long long)EL * 8, TB), TB>>>(xp[cur], xg[cur],
                                                         label_src, label_dst,
                                                         (float*)d_out, EL);
}

// round 7
// speedup vs baseline: 2.3711x; 1.3245x over previous
#include <cuda_runtime.h>
#include <cstdint>

typedef unsigned long long ull;
typedef long long ll;

// Problem constants (GB300 bench shapes)
#define DD     64
#define NP_MAX 100000
#define NG_MAX 40000
#define E_MAX  1600000
#define RPW    4            // rows per warp in fused update

// ---------------- static scratch (no runtime allocation allowed) -------------
__device__ float g_xp[2][NP_MAX * DD];
__device__ float g_xg[2][NG_MAX * DD];
__device__ int   g_cnt_p[NP_MAX];
__device__ int   g_cnt_g[NG_MAX];
__device__ int   g_off_g[NG_MAX + 1];
__device__ int   g_off_p[NP_MAX + 1];
__device__ int   g_cur_g[NG_MAX];
__device__ int   g_cur_p[NP_MAX];
__device__ int   g_csr_pg[E_MAX];
__device__ int   g_csr_gp[E_MAX];

// ---------------- f32x2 helpers (sm_103a packed FMA only via PTX) -------------
__device__ __forceinline__ ull pack2(float lo, float hi) {
    ull r; asm("mov.b64 %0, {%1, %2};" : "=l"(r) : "f"(lo), "f"(hi)); return r;
}
__device__ __forceinline__ void unpack2(ull v, float& lo, float& hi) {
    asm("mov.b64 {%0, %1}, %2;" : "=f"(lo), "=f"(hi) : "l"(v));
}
__device__ __forceinline__ void ffma2(ull& d, ull a, ull b) {   // d = a*b + d (2x fp32)
    asm("fma.rn.f32x2 %0, %1, %2, %0;" : "+l"(d) : "l"(a), "l"(b));
}
__device__ __forceinline__ void fadd2(ull& d, ull a) {          // d += a
    asm("add.rn.f32x2 %0, %0, %1;" : "+l"(d) : "l"(a));
}
__device__ __forceinline__ void fmul2(ull& d, ull a) {          // d *= a
    asm("mul.rn.f32x2 %0, %0, %1;" : "+l"(d) : "l"(a));
}

// ---------------- small utility kernels --------------------------------------
__global__ void zero2_kernel(int* a, int na, int* b, int nb) {
    int i = blockIdx.x * blockDim.x + threadIdx.x;
    if (i < na) a[i] = 0;
    else if (i - na < nb) b[i - na] = 0;
}

// both histograms in one launch
__global__ void hist2_kernel(const int* __restrict__ d0, int* __restrict__ c0,
                             const int* __restrict__ d1, int* __restrict__ c1, int E) {
    int i = blockIdx.x * blockDim.x + threadIdx.x;
    if (i < E) atomicAdd(&c0[d0[i]], 1);
    else if (i < 2 * E) atomicAdd(&c1[d1[i - E]], 1);
}

// single-block exclusive scan, 4 elements/thread per iteration
__global__ void scan_kernel(const int* __restrict__ cnt, int* __restrict__ off,
                            int* __restrict__ cursor, int n) {
    __shared__ int warp_sums[32];
    __shared__ int s_carry;
    int tid = threadIdx.x;           // 1024 threads
    int lane = tid & 31, warp = tid >> 5;
    if (tid == 0) s_carry = 0;
    __syncthreads();
    for (int base = 0; base < n; base += 4096) {
        int i0 = base + tid * 4;
        int v[4];
#pragma unroll
        for (int j = 0; j < 4; j++) v[j] = (i0 + j < n) ? cnt[i0 + j] : 0;
        int t = v[0] + v[1] + v[2] + v[3];
        int x = t;
#pragma unroll
        for (int o = 1; o < 32; o <<= 1) {
            int y = __shfl_up_sync(0xffffffffu, x, o);
            if (lane >= o) x += y;
        }
        if (lane == 31) warp_sums[warp] = x;
        __syncthreads();
        if (warp == 0) {
            int w = warp_sums[lane];
#pragma unroll
            for (int o = 1; o < 32; o <<= 1) {
                int y = __shfl_up_sync(0xffffffffu, w, o);
                if (lane >= o) w += y;
            }
            warp_sums[lane] = w;
        }
        __syncthreads();
        int run = x - t + (warp > 0 ? warp_sums[warp - 1] : 0) + s_carry;
#pragma unroll
        for (int j = 0; j < 4; j++) {
            if (i0 + j < n) { off[i0 + j] = run; cursor[i0 + j] = run; }
            run += v[j];
        }
        __syncthreads();
        if (tid == 0) s_carry += warp_sums[31];
        __syncthreads();
    }
    if (tid == 0) off[n] = s_carry;
}

// both CSR fills in one launch
__global__ void fill2_kernel(const int* __restrict__ s0, const int* __restrict__ d0,
                             int* __restrict__ cu0, int* __restrict__ cs0,
                             const int* __restrict__ s1, const int* __restrict__ d1,
                             int* __restrict__ cu1, int* __restrict__ cs1, int E) {
    int i = blockIdx.x * blockDim.x + threadIdx.x;
    if (i < E) {
        int pos = atomicAdd(&cu0[d0[i]], 1);
        cs0[pos] = s0[i];
    } else if (i < 2 * E) {
        int j = i - E;
        int pos = atomicAdd(&cu1[d1[j]], 1);
        cs1[pos] = s1[j];
    }
}

// xp0[i,:] = protein_emb[nid[i],:]  (float4 vectorized)
__global__ void init_xp_kernel(const float* __restrict__ pe, const int* __restrict__ nid,
                               float* __restrict__ out, int np) {
    long long idx = (long long)blockIdx.x * blockDim.x + threadIdx.x;
    long long n = (long long)np * 16;
    if (idx >= n) return;
    int r = (int)(idx >> 4);
    int j = (int)(idx & 15);
    const float4* src = (const float4*)(pe + (ll)nid[r] * DD);
    ((float4*)(out + (ll)r * DD))[j] = __ldg(src + j);
}

// ---------------- xg init GEMM: [M,K] @ [K,64] + bias + emb[nid] -------------
// f32x2 packed accumulators: thread covers 4 rows x col-pairs {(2tx,2tx+32),(2tx+1,2tx+33)}
#define GBK 8
__global__ void gemm_xg_kernel(const float* __restrict__ A, const float* __restrict__ W,
                               const float* __restrict__ bias, const float* __restrict__ emb,
                               const int* __restrict__ nid, float* __restrict__ out,
                               int M, int K) {
    __shared__ float As[GBK][68];
    __shared__ __align__(16) float sB[GBK][32][2];   // sB[k][pair][comp]: comp0=col pair, comp1=col pair+32
    int tid = threadIdx.x;          // 256 threads
    int tx = tid & 15;
    int ty = tid >> 4;
    int rowBase = blockIdx.x * 64;

    ull acc[4][2];
#pragma unroll
    for (int i = 0; i < 4; i++) { acc[i][0] = 0ull; acc[i][1] = 0ull; }

    int la_row = tid >> 2;
    int la_k   = (tid & 3) * 2;
    int lb_k   = tid >> 5;
    int lb_c   = (tid & 31) * 2;

    const float* Arow = A + (ll)(rowBase + la_row) * K;
    bool a_ok = (rowBase + la_row) < M;

    for (int k0 = 0; k0 < K; k0 += GBK) {
        float a0 = 0.f, a1 = 0.f;
        if (a_ok) { a0 = Arow[k0 + la_k]; a1 = Arow[k0 + la_k + 1]; }
        As[la_k][la_row] = a0;
        As[la_k + 1][la_row] = a1;
        {
            float w0 = W[(ll)(k0 + lb_k) * 64 + lb_c];
            float w1 = W[(ll)(k0 + lb_k) * 64 + lb_c + 1];
            sB[lb_k][lb_c & 31][lb_c >> 5]       = w0;
            sB[lb_k][(lb_c + 1) & 31][(lb_c + 1) >> 5] = w1;
        }
        __syncthreads();
#pragma unroll
        for (int k = 0; k < GBK; k++) {
            float4 av = *(const float4*)&As[k][ty * 4];
            longlong2 bv = *(const longlong2*)&sB[k][2 * tx][0];
            ull b0 = (ull)bv.x, b1 = (ull)bv.y;
            ull p0 = pack2(av.x, av.x);
            ull p1 = pack2(av.y, av.y);
            ull p2 = pack2(av.z, av.z);
            ull p3 = pack2(av.w, av.w);
            ffma2(acc[0][0], p0, b0); ffma2(acc[0][1], p0, b1);
            ffma2(acc[1][0], p1, b0); ffma2(acc[1][1], p1, b1);
            ffma2(acc[2][0], p2, b0); ffma2(acc[2][1], p2, b1);
            ffma2(acc[3][0], p3, b0); ffma2(acc[3][1], p3, b1);
        }
        __syncthreads();
    }

#pragma unroll
    for (int i = 0; i < 4; i++) {
        int r = rowBase + ty * 4 + i;
        if (r >= M) continue;
        int g = nid[r];
#pragma unroll
        for (int j = 0; j < 2; j++) {
            float lo, hi; unpack2(acc[i][j], lo, hi);
            int cl = 2 * tx + j, ch = 2 * tx + j + 32;
            out[(ll)r * 64 + cl] = lo + bias[cl] + emb[(ll)g * 64 + cl];
            out[(ll)r * 64 + ch] = hi + bias[ch] + emb[(ll)g * 64 + ch];
        }
    }
}

// --------- fused mean-aggregate + node update (R=4 rows/warp, f32x2) ---------
// lane holds cols (2*lane, 2*lane+1); W smem read amortized over RPW rows
__global__ void __launch_bounds__(512, 2) agg_update_kernel(
    const float* __restrict__ xsrc, const float* __restrict__ xdst,
    const int* __restrict__ off, const int* __restrict__ csr,
    const float* __restrict__ Wl, const float* __restrict__ bl,
    const float* __restrict__ Wr,
    float* __restrict__ out, int n, int do_relu) {
    // sW[(k*32+pair)*4 + {0,1,2,3}] = {Wl[k][2p], Wl[k][2p+1], Wr[k][2p], Wr[k][2p+1]}
    __shared__ __align__(16) float sW[64 * 128];
    for (int idx = threadIdx.x; idx < 4096; idx += blockDim.x) {
        int k = idx >> 6, c = idx & 63;
        float* d = &sW[(k * 32 + (c >> 1)) * 4];
        d[c & 1]       = Wl[idx];
        d[2 + (c & 1)] = Wr[idx];
    }
    __syncthreads();

    int warp = threadIdx.x >> 5;
    int lane = threadIdx.x & 31;
    int wpb = blockDim.x >> 5;
    int gwarp = blockIdx.x * wpb + warp;
    int nwarp = gridDim.x * wpb;
    int ngroups = (n + RPW - 1) / RPW;

    float bl_lo = __ldg(&bl[2 * lane]);
    float bl_hi = __ldg(&bl[2 * lane + 1]);
    ull binit = pack2(bl_lo, bl_hi);

    for (int g = gwarp; g < ngroups; g += nwarp) {
        int row0 = g * RPW;
        float2 af[RPW], xf[RPW];

        // ---- gather + mean for RPW rows ----
#pragma unroll
        for (int r = 0; r < RPW; r++) {
            int row = row0 + r;
            ull aa0 = 0ull, aa1 = 0ull;
            float2 xx = make_float2(0.f, 0.f);
            float ic = 0.f;
            if (row < n) {
                int e0 = __ldg(&off[row]);
                int e1 = __ldg(&off[row + 1]);
                int e = e0;
                for (; e + 4 <= e1; e += 4) {
                    int s0 = __ldg(&csr[e]);
                    int s1 = __ldg(&csr[e + 1]);
                    int s2 = __ldg(&csr[e + 2]);
                    int s3 = __ldg(&csr[e + 3]);
                    ull v0 = __ldg((const ull*)(xsrc + (ll)s0 * DD) + lane);
                    ull v1 = __ldg((const ull*)(xsrc + (ll)s1 * DD) + lane);
                    ull v2 = __ldg((const ull*)(xsrc + (ll)s2 * DD) + lane);
                    ull v3 = __ldg((const ull*)(xsrc + (ll)s3 * DD) + lane);
                    fadd2(aa0, v0); fadd2(aa1, v1); fadd2(aa0, v2); fadd2(aa1, v3);
                }
                for (; e < e1; e++) {
                    int s = __ldg(&csr[e]);
                    fadd2(aa0, __ldg((const ull*)(xsrc + (ll)s * DD) + lane));
                }
                ic = 1.0f / (float)max(e1 - e0, 1);
                xx = __ldg((const float2*)(xdst + (ll)row * DD) + lane);
            }
            fadd2(aa0, aa1);
            fmul2(aa0, pack2(ic, ic));
            unpack2(aa0, af[r].x, af[r].y);
            xf[r] = xx;
        }

        // ---- matvec: acc = a @ Wl + x @ Wr (+ bias) ----
        ull acc[RPW];
#pragma unroll
        for (int r = 0; r < RPW; r++) acc[r] = binit;

#pragma unroll 4
        for (int k = 0; k < 64; k++) {
            longlong2 wv = *(const longlong2*)&sW[(k * 32 + lane) * 4];
            ull wl2 = (ull)wv.x, wr2 = (ull)wv.y;
            int sl = k >> 1;
#pragma unroll
            for (int r = 0; r < RPW; r++) {
                float av = (k & 1) ? __shfl_sync(0xffffffffu, af[r].y, sl)
                                   : __shfl_sync(0xffffffffu, af[r].x, sl);
                float xv = (k & 1) ? __shfl_sync(0xffffffffu, xf[r].y, sl)
                                   : __shfl_sync(0xffffffffu, xf[r].x, sl);
                ffma2(acc[r], pack2(av, av), wl2);
                ffma2(acc[r], pack2(xv, xv), wr2);
            }
        }

#pragma unroll
        for (int r = 0; r < RPW; r++) {
            int row = row0 + r;
            if (row < n) {
                float lo, hi; unpack2(acc[r], lo, hi);
                if (do_relu) { lo = fmaxf(lo, 0.0f); hi = fmaxf(hi, 0.0f); }
                float2 o; o.x = lo; o.y = hi;
                *((float2*)(out + (ll)row * DD) + lane) = o;
            }
        }
    }
}

// ---------------- classifier: out[e] = dot(xp[ls[e]], xg[ld[e]]) (8 thr/edge)
__global__ void classify_kernel(const float* __restrict__ xp, const float* __restrict__ xg,
                                const int* __restrict__ ls, const int* __restrict__ ld,
                                float* __restrict__ out, int E) {
    long long idx = (long long)blockIdx.x * blockDim.x + threadIdx.x;
    long long total = (long long)E * 8;
    if (idx >= total) return;
    int e = (int)(idx >> 3);
    int j = (int)(idx & 7);
    int a = __ldg(&ls[e]);
    int b = __ldg(&ld[e]);
    const float4* pa = (const float4*)(xp + (ll)a * DD);
    const float4* pb = (const float4*)(xg + (ll)b * DD);
    float4 u0 = __ldg(pa + j * 2);
    float4 u1 = __ldg(pa + j * 2 + 1);
    float4 v0 = __ldg(pb + j * 2);
    float4 v1 = __ldg(pb + j * 2 + 1);
    float s = u0.x * v0.x + u0.y * v0.y + u0.z * v0.z + u0.w * v0.w
            + u1.x * v1.x + u1.y * v1.y + u1.z * v1.z + u1.w * v1.w;
    s += __shfl_xor_sync(0xffffffffu, s, 4);
    s += __shfl_xor_sync(0xffffffffu, s, 2);
    s += __shfl_xor_sync(0xffffffffu, s, 1);
    if (j == 0) out[e] = s;
}

// ---------------- host driver ------------------------------------------------
static inline int cdiv(long long a, int b) { return (int)((a + b - 1) / b); }

extern "C" void kernel_launch(void* const* d_in, const int* in_sizes, int n_in,
                              void* d_out, int out_size) {
    const float* go_x        = (const float*)d_in[0];
    const float* protein_emb = (const float*)d_in[1];
    const float* go_emb      = (const float*)d_in[2];
    const float* lin_W       = (const float*)d_in[3];
    const float* lin_b       = (const float*)d_in[4];
    const float* Wl          = (const float*)d_in[5];
    const float* bl          = (const float*)d_in[6];
    const float* Wr          = (const float*)d_in[7];
    const int*   protein_nid = (const int*)d_in[8];
    const int*   go_nid      = (const int*)d_in[9];
    const int*   src_pg      = (const int*)d_in[10];
    const int*   dst_pg      = (const int*)d_in[11];
    const int*   src_gp      = (const int*)d_in[12];
    const int*   dst_gp      = (const int*)d_in[13];
    const int*   label_src   = (const int*)d_in[14];
    const int*   label_dst   = (const int*)d_in[15];

    int NP = in_sizes[8];
    int NG = in_sizes[9];
    int E  = in_sizes[10];
    int EL = in_sizes[14];
    int K  = (int)((long long)in_sizes[0] / NG);
    int L  = (int)((long long)in_sizes[5] / (2 * 64 * 64));

    float *xp_buf, *xg_buf;
    int *cnt_p, *cnt_g, *off_g, *off_p, *cur_g, *cur_p, *csr_pg, *csr_gp;
    cudaGetSymbolAddress((void**)&xp_buf, g_xp);
    cudaGetSymbolAddress((void**)&xg_buf, g_xg);
    cudaGetSymbolAddress((void**)&cnt_p, g_cnt_p);
    cudaGetSymbolAddress((void**)&cnt_g, g_cnt_g);
    cudaGetSymbolAddress((void**)&off_g, g_off_g);
    cudaGetSymbolAddress((void**)&off_p, g_off_p);
    cudaGetSymbolAddress((void**)&cur_g, g_cur_g);
    cudaGetSymbolAddress((void**)&cur_p, g_cur_p);
    cudaGetSymbolAddress((void**)&csr_pg, g_csr_pg);
    cudaGetSymbolAddress((void**)&csr_gp, g_csr_gp);

    float* xp[2] = { xp_buf, xp_buf + (ll)NP_MAX * DD };
    float* xg[2] = { xg_buf, xg_buf + (ll)NG_MAX * DD };

    const int TB = 256;

    // ---- CSR build (reused by all layers) ----
    zero2_kernel<<<cdiv(NG + NP, TB), TB>>>(cnt_g, NG, cnt_p, NP);
    hist2_kernel<<<cdiv(2LL * E, TB), TB>>>(dst_pg, cnt_g, dst_gp, cnt_p, E);
    scan_kernel<<<1, 1024>>>(cnt_g, off_g, cur_g, NG);
    scan_kernel<<<1, 1024>>>(cnt_p, off_p, cur_p, NP);
    fill2_kernel<<<cdiv(2LL * E, TB), TB>>>(src_pg, dst_pg, cur_g, csr_pg,
                                            src_gp, dst_gp, cur_p, csr_gp, E);

    // ---- input embeddings ----
    init_xp_kernel<<<cdiv((ll)NP * 16, TB), TB>>>(protein_emb, protein_nid, xp[0], NP);
    gemm_xg_kernel<<<cdiv(NG, 64), 256>>>(go_x, lin_W, lin_b, go_emb, go_nid, xg[0], NG, K);

    // ---- layers ----
    int cur = 0;
    for (int l = 0; l < L; l++) {
        int nxt = cur ^ 1;
        int relu = (l < L - 1) ? 1 : 0;
        agg_update_kernel<<<370, 512>>>(xp[cur], xg[cur], off_g, csr_pg,
                                        Wl + (ll)(l * 2 + 0) * 64 * 64,
                                        bl + (ll)(l * 2 + 0) * 64,
                                        Wr + (ll)(l * 2 + 0) * 64 * 64,
                                        xg[nxt], NG, relu);
        agg_update_kernel<<<370, 512>>>(xg[cur], xp[cur], off_p, csr_gp,
                                        Wl + (ll)(l * 2 + 1) * 64 * 64,
                                        bl + (ll)(l * 2 + 1) * 64,
                                        Wr + (ll)(l * 2 + 1) * 64 * 64,
                                        xp[nxt], NP, relu);
        cur = nxt;
    }

    classify_kernel<<<cdiv((ll)EL * 8, TB), TB>>>(xp[cur], xg[cur],
                                                  label_src, label_dst,
                                                  (float*)d_out, EL);
}

// round 8
// speedup vs baseline: 2.3970x; 1.0109x over previous
#include <cuda_runtime.h>
#include <cstdint>

typedef unsigned long long ull;
typedef long long ll;

// Problem constants (GB300 bench shapes)
#define DD     64
#define NP_MAX 100000
#define NG_MAX 40000
#define E_MAX  1600000
#define RPW    4            // rows per warp in fused update

// ---------------- static scratch (no runtime allocation allowed) -------------
__device__ float g_xp[2][NP_MAX * DD];
__device__ float g_xg[2][NG_MAX * DD];
__device__ int   g_cnt_p[NP_MAX];
__device__ int   g_cnt_g[NG_MAX];
__device__ int   g_off_g[NG_MAX + 1];
__device__ int   g_off_p[NP_MAX + 1];
__device__ int   g_cur_g[NG_MAX];
__device__ int   g_cur_p[NP_MAX];
__device__ int   g_csr_pg[E_MAX];
__device__ int   g_csr_gp[E_MAX];
__device__ int   g_bsum_g[64];
__device__ int   g_bsum_p[64];

// ---------------- f32x2 helpers (sm_103a packed FMA only via PTX) -------------
__device__ __forceinline__ ull pack2(float lo, float hi) {
    ull r; asm("mov.b64 %0, {%1, %2};" : "=l"(r) : "f"(lo), "f"(hi)); return r;
}
__device__ __forceinline__ void unpack2(ull v, float& lo, float& hi) {
    asm("mov.b64 {%0, %1}, %2;" : "=f"(lo), "=f"(hi) : "l"(v));
}
__device__ __forceinline__ void ffma2(ull& d, ull a, ull b) {   // d = a*b + d (2x fp32)
    asm("fma.rn.f32x2 %0, %1, %2, %0;" : "+l"(d) : "l"(a), "l"(b));
}
__device__ __forceinline__ void fadd2(ull& d, ull a) {          // d += a
    asm("add.rn.f32x2 %0, %0, %1;" : "+l"(d) : "l"(a));
}
__device__ __forceinline__ void fmul2(ull& d, ull a) {          // d *= a
    asm("mul.rn.f32x2 %0, %0, %1;" : "+l"(d) : "l"(a));
}

// ---------------- small utility kernels --------------------------------------
__global__ void zero2_kernel(int* a, int na, int* b, int nb) {
    int i = blockIdx.x * blockDim.x + threadIdx.x;
    if (i < na) a[i] = 0;
    else if (i - na < nb) b[i - na] = 0;
}

// both histograms in one launch
__global__ void hist2_kernel(const int* __restrict__ d0, int* __restrict__ c0,
                             const int* __restrict__ d1, int* __restrict__ c1, int E) {
    int i = blockIdx.x * blockDim.x + threadIdx.x;
    if (i < E) atomicAdd(&c0[d0[i]], 1);
    else if (i < 2 * E) atomicAdd(&c1[d1[i - E]], 1);
}

// ---------------- multi-block exclusive scan (3 phases) ----------------------
// phase 1: per-block (4096-elem chunk) sum
__global__ void scan_reduce_kernel(const int* __restrict__ cnt, int* __restrict__ bsum, int n) {
    __shared__ int ws[16];
    int base = blockIdx.x * 4096;
    int s = 0;
    for (int i = threadIdx.x; i < 4096; i += 512) {
        int j = base + i;
        if (j < n) s += cnt[j];
    }
#pragma unroll
    for (int o = 16; o; o >>= 1) s += __shfl_down_sync(0xffffffffu, s, o);
    if ((threadIdx.x & 31) == 0) ws[threadIdx.x >> 5] = s;
    __syncthreads();
    if (threadIdx.x < 16) {
        s = ws[threadIdx.x];
#pragma unroll
        for (int o = 8; o; o >>= 1) s += __shfl_down_sync(0xffffu, s, o);
        if (threadIdx.x == 0) bsum[blockIdx.x] = s;
    }
}

// phase 2: single-warp exclusive scan of block sums (nb <= 32); total -> *off_n
__global__ void scan_bsum_kernel(int* __restrict__ bsum, int nb, int* __restrict__ off_n) {
    int tid = threadIdx.x;
    int v = (tid < nb) ? bsum[tid] : 0;
    int x = v;
#pragma unroll
    for (int o = 1; o < 32; o <<= 1) {
        int y = __shfl_up_sync(0xffffffffu, x, o);
        if (tid >= o) x += y;
    }
    if (tid < nb) bsum[tid] = x - v;
    if (tid == 31) *off_n = x;
}

// phase 3: per-block local exclusive scan + block prefix; writes off and cursor
__global__ void scan_apply_kernel(const int* __restrict__ cnt, const int* __restrict__ bsum,
                                  int* __restrict__ off, int* __restrict__ cursor, int n) {
    __shared__ int ws[16];
    int base = blockIdx.x * 4096 + threadIdx.x * 8;
    int v[8]; int t = 0;
#pragma unroll
    for (int j = 0; j < 8; j++) {
        int i = base + j;
        v[j] = (i < n) ? cnt[i] : 0;
        t += v[j];
    }
    int lane = threadIdx.x & 31, warp = threadIdx.x >> 5;
    int x = t;
#pragma unroll
    for (int o = 1; o < 32; o <<= 1) {
        int y = __shfl_up_sync(0xffffffffu, x, o);
        if (lane >= o) x += y;
    }
    if (lane == 31) ws[warp] = x;
    __syncthreads();
    if (warp == 0 && lane < 16) {
        int w = ws[lane];
#pragma unroll
        for (int o = 1; o < 16; o <<= 1) {
            int y = __shfl_up_sync(0xffffu, w, o);
            if (lane >= o) w += y;
        }
        ws[lane] = w;
    }
    __syncthreads();
    int run = x - t + (warp ? ws[warp - 1] : 0) + bsum[blockIdx.x];
#pragma unroll
    for (int j = 0; j < 8; j++) {
        int i = base + j;
        if (i < n) { off[i] = run; cursor[i] = run; }
        run += v[j];
    }
}

// both CSR fills in one launch
__global__ void fill2_kernel(const int* __restrict__ s0, const int* __restrict__ d0,
                             int* __restrict__ cu0, int* __restrict__ cs0,
                             const int* __restrict__ s1, const int* __restrict__ d1,
                             int* __restrict__ cu1, int* __restrict__ cs1, int E) {
    int i = blockIdx.x * blockDim.x + threadIdx.x;
    if (i < E) {
        int pos = atomicAdd(&cu0[d0[i]], 1);
        cs0[pos] = s0[i];
    } else if (i < 2 * E) {
        int j = i - E;
        int pos = atomicAdd(&cu1[d1[j]], 1);
        cs1[pos] = s1[j];
    }
}

// xp0[i,:] = protein_emb[nid[i],:]  (float4 vectorized)
__global__ void init_xp_kernel(const float* __restrict__ pe, const int* __restrict__ nid,
                               float* __restrict__ out, int np) {
    long long idx = (long long)blockIdx.x * blockDim.x + threadIdx.x;
    long long n = (long long)np * 16;
    if (idx >= n) return;
    int r = (int)(idx >> 4);
    int j = (int)(idx & 15);
    const float4* src = (const float4*)(pe + (ll)nid[r] * DD);
    ((float4*)(out + (ll)r * DD))[j] = __ldg(src + j);
}

// ---------------- xg init GEMM: [M,K] @ [K,64] + bias + emb[nid] -------------
#define GBK 8
__global__ void gemm_xg_kernel(const float* __restrict__ A, const float* __restrict__ W,
                               const float* __restrict__ bias, const float* __restrict__ emb,
                               const int* __restrict__ nid, float* __restrict__ out,
                               int M, int K) {
    __shared__ float As[GBK][68];
    __shared__ __align__(16) float sB[GBK][32][2];
    int tid = threadIdx.x;          // 256 threads
    int tx = tid & 15;
    int ty = tid >> 4;
    int rowBase = blockIdx.x * 64;

    ull acc[4][2];
#pragma unroll
    for (int i = 0; i < 4; i++) { acc[i][0] = 0ull; acc[i][1] = 0ull; }

    int la_row = tid >> 2;
    int la_k   = (tid & 3) * 2;
    int lb_k   = tid >> 5;
    int lb_c   = (tid & 31) * 2;

    const float* Arow = A + (ll)(rowBase + la_row) * K;
    bool a_ok = (rowBase + la_row) < M;

    for (int k0 = 0; k0 < K; k0 += GBK) {
        float a0 = 0.f, a1 = 0.f;
        if (a_ok) { a0 = Arow[k0 + la_k]; a1 = Arow[k0 + la_k + 1]; }
        As[la_k][la_row] = a0;
        As[la_k + 1][la_row] = a1;
        {
            float w0 = W[(ll)(k0 + lb_k) * 64 + lb_c];
            float w1 = W[(ll)(k0 + lb_k) * 64 + lb_c + 1];
            sB[lb_k][lb_c & 31][lb_c >> 5]       = w0;
            sB[lb_k][(lb_c + 1) & 31][(lb_c + 1) >> 5] = w1;
        }
        __syncthreads();
#pragma unroll
        for (int k = 0; k < GBK; k++) {
            float4 av = *(const float4*)&As[k][ty * 4];
            longlong2 bv = *(const longlong2*)&sB[k][2 * tx][0];
            ull b0 = (ull)bv.x, b1 = (ull)bv.y;
            ull p0 = pack2(av.x, av.x);
            ull p1 = pack2(av.y, av.y);
            ull p2 = pack2(av.z, av.z);
            ull p3 = pack2(av.w, av.w);
            ffma2(acc[0][0], p0, b0); ffma2(acc[0][1], p0, b1);
            ffma2(acc[1][0], p1, b0); ffma2(acc[1][1], p1, b1);
            ffma2(acc[2][0], p2, b0); ffma2(acc[2][1], p2, b1);
            ffma2(acc[3][0], p3, b0); ffma2(acc[3][1], p3, b1);
        }
        __syncthreads();
    }

#pragma unroll
    for (int i = 0; i < 4; i++) {
        int r = rowBase + ty * 4 + i;
        if (r >= M) continue;
        int g = nid[r];
#pragma unroll
        for (int j = 0; j < 2; j++) {
            float lo, hi; unpack2(acc[i][j], lo, hi);
            int cl = 2 * tx + j, ch = 2 * tx + j + 32;
            out[(ll)r * 64 + cl] = lo + bias[cl] + emb[(ll)g * 64 + cl];
            out[(ll)r * 64 + ch] = hi + bias[ch] + emb[(ll)g * 64 + ch];
        }
    }
}

// --------- fused mean-aggregate + node update (R=4 rows/warp, f32x2) ---------
// Matvec uses smem-broadcast of pre-duplicated (a,a)/(x,x) operands: no SHFL.
// Dynamic smem: sW 32KB + sAX 64KB (16 warps x 4 rows x 64 k x 2 ull)
__global__ void __launch_bounds__(512, 2) agg_update_kernel(
    const float* __restrict__ xsrc, const float* __restrict__ xdst,
    const int* __restrict__ off, const int* __restrict__ csr,
    const float* __restrict__ Wl, const float* __restrict__ bl,
    const float* __restrict__ Wr,
    float* __restrict__ out, int n, int do_relu) {
    extern __shared__ __align__(16) float smem_dyn[];
    float* sW = smem_dyn;                       // 8192 floats = 32KB
    ull*   sAX = (ull*)(smem_dyn + 8192);       // 8192 ull = 64KB

    // sW[(k*32+pair)*4 + {0,1,2,3}] = {Wl[k][2p], Wl[k][2p+1], Wr[k][2p], Wr[k][2p+1]}
    for (int idx = threadIdx.x; idx < 4096; idx += blockDim.x) {
        int k = idx >> 6, c = idx & 63;
        float* d = &sW[(k * 32 + (c >> 1)) * 4];
        d[c & 1]       = Wl[idx];
        d[2 + (c & 1)] = Wr[idx];
    }
    __syncthreads();

    int warp = threadIdx.x >> 5;
    int lane = threadIdx.x & 31;
    int wpb = blockDim.x >> 5;
    int gwarp = blockIdx.x * wpb + warp;
    int nwarp = gridDim.x * wpb;
    int ngroups = (n + RPW - 1) / RPW;

    ull* myAX = sAX + warp * (RPW * 64 * 2);    // 512 ull per warp

    float bl_lo = __ldg(&bl[2 * lane]);
    float bl_hi = __ldg(&bl[2 * lane + 1]);
    ull binit = pack2(bl_lo, bl_hi);

    for (int g = gwarp; g < ngroups; g += nwarp) {
        int row0 = g * RPW;
        float2 af[RPW], xf[RPW];

        // ---- gather + mean for RPW rows ----
#pragma unroll
        for (int r = 0; r < RPW; r++) {
            int row = row0 + r;
            ull aa0 = 0ull, aa1 = 0ull;
            float2 xx = make_float2(0.f, 0.f);
            float ic = 0.f;
            if (row < n) {
                int e0 = __ldg(&off[row]);
                int e1 = __ldg(&off[row + 1]);
                int e = e0;
                for (; e + 4 <= e1; e += 4) {
                    int s0 = __ldg(&csr[e]);
                    int s1 = __ldg(&csr[e + 1]);
                    int s2 = __ldg(&csr[e + 2]);
                    int s3 = __ldg(&csr[e + 3]);
                    ull v0 = __ldg((const ull*)(xsrc + (ll)s0 * DD) + lane);
                    ull v1 = __ldg((const ull*)(xsrc + (ll)s1 * DD) + lane);
                    ull v2 = __ldg((const ull*)(xsrc + (ll)s2 * DD) + lane);
                    ull v3 = __ldg((const ull*)(xsrc + (ll)s3 * DD) + lane);
                    fadd2(aa0, v0); fadd2(aa1, v1); fadd2(aa0, v2); fadd2(aa1, v3);
                }
                for (; e < e1; e++) {
                    int s = __ldg(&csr[e]);
                    fadd2(aa0, __ldg((const ull*)(xsrc + (ll)s * DD) + lane));
                }
                ic = 1.0f / (float)max(e1 - e0, 1);
                xx = __ldg((const float2*)(xdst + (ll)row * DD) + lane);
            }
            fadd2(aa0, aa1);
            fmul2(aa0, pack2(ic, ic));
            unpack2(aa0, af[r].x, af[r].y);
            xf[r] = xx;
        }

        // ---- stage duplicated operands to smem: lane l owns k=2l, 2l+1 ----
        __syncwarp();
#pragma unroll
        for (int r = 0; r < RPW; r++) {
            ulonglong2 s0, s1;
            s0.x = pack2(af[r].x, af[r].x); s0.y = pack2(xf[r].x, xf[r].x);
            s1.x = pack2(af[r].y, af[r].y); s1.y = pack2(xf[r].y, xf[r].y);
            *(ulonglong2*)&myAX[(r * 64 + 2 * lane) * 2]     = s0;
            *(ulonglong2*)&myAX[(r * 64 + 2 * lane + 1) * 2] = s1;
        }
        __syncwarp();

        // ---- matvec: acc = a @ Wl + x @ Wr (+ bias), smem broadcast ----
        ull acc[RPW];
#pragma unroll
        for (int r = 0; r < RPW; r++) acc[r] = binit;

#pragma unroll 4
        for (int k = 0; k < 64; k++) {
            longlong2 wv = *(const longlong2*)&sW[(k * 32 + lane) * 4];
            ull wl2 = (ull)wv.x, wr2 = (ull)wv.y;
#pragma unroll
            for (int r = 0; r < RPW; r++) {
                ulonglong2 ax = *(const ulonglong2*)&myAX[(r * 64 + k) * 2];
                ffma2(acc[r], (ull)ax.x, wl2);
                ffma2(acc[r], (ull)ax.y, wr2);
            }
        }

#pragma unroll
        for (int r = 0; r < RPW; r++) {
            int row = row0 + r;
            if (row < n) {
                float lo, hi; unpack2(acc[r], lo, hi);
                if (do_relu) { lo = fmaxf(lo, 0.0f); hi = fmaxf(hi, 0.0f); }
                float2 o; o.x = lo; o.y = hi;
                *((float2*)(out + (ll)row * DD) + lane) = o;
            }
        }
    }
}

// ---------------- classifier: out[e] = dot(xp[ls[e]], xg[ld[e]]) (8 thr/edge)
__global__ void classify_kernel(const float* __restrict__ xp, const float* __restrict__ xg,
                                const int* __restrict__ ls, const int* __restrict__ ld,
                                float* __restrict__ out, int E) {
    long long idx = (long long)blockIdx.x * blockDim.x + threadIdx.x;
    long long total = (long long)E * 8;
    if (idx >= total) return;
    int e = (int)(idx >> 3);
    int j = (int)(idx & 7);
    int a = __ldg(&ls[e]);
    int b = __ldg(&ld[e]);
    const float4* pa = (const float4*)(xp + (ll)a * DD);
    const float4* pb = (const float4*)(xg + (ll)b * DD);
    float4 u0 = __ldg(pa + j * 2);
    float4 u1 = __ldg(pa + j * 2 + 1);
    float4 v0 = __ldg(pb + j * 2);
    float4 v1 = __ldg(pb + j * 2 + 1);
    float s = u0.x * v0.x + u0.y * v0.y + u0.z * v0.z + u0.w * v0.w
            + u1.x * v1.x + u1.y * v1.y + u1.z * v1.z + u1.w * v1.w;
    s += __shfl_xor_sync(0xffffffffu, s, 4);
    s += __shfl_xor_sync(0xffffffffu, s, 2);
    s += __shfl_xor_sync(0xffffffffu, s, 1);
    if (j == 0) out[e] = s;
}

// ---------------- host driver ------------------------------------------------
static inline int cdiv(long long a, int b) { return (int)((a + b - 1) / b); }

extern "C" void kernel_launch(void* const* d_in, const int* in_sizes, int n_in,
                              void* d_out, int out_size) {
    const float* go_x        = (const float*)d_in[0];
    const float* protein_emb = (const float*)d_in[1];
    const float* go_emb      = (const float*)d_in[2];
    const float* lin_W       = (const float*)d_in[3];
    const float* lin_b       = (const float*)d_in[4];
    const float* Wl          = (const float*)d_in[5];
    const float* bl          = (const float*)d_in[6];
    const float* Wr          = (const float*)d_in[7];
    const int*   protein_nid = (const int*)d_in[8];
    const int*   go_nid      = (const int*)d_in[9];
    const int*   src_pg      = (const int*)d_in[10];
    const int*   dst_pg      = (const int*)d_in[11];
    const int*   src_gp      = (const int*)d_in[12];
    const int*   dst_gp      = (const int*)d_in[13];
    const int*   label_src   = (const int*)d_in[14];
    const int*   label_dst   = (const int*)d_in[15];

    int NP = in_sizes[8];
    int NG = in_sizes[9];
    int E  = in_sizes[10];
    int EL = in_sizes[14];
    int K  = (int)((long long)in_sizes[0] / NG);
    int L  = (int)((long long)in_sizes[5] / (2 * 64 * 64));

    float *xp_buf, *xg_buf;
    int *cnt_p, *cnt_g, *off_g, *off_p, *cur_g, *cur_p, *csr_pg, *csr_gp;
    int *bsum_g, *bsum_p;
    cudaGetSymbolAddress((void**)&xp_buf, g_xp);
    cudaGetSymbolAddress((void**)&xg_buf, g_xg);
    cudaGetSymbolAddress((void**)&cnt_p, g_cnt_p);
    cudaGetSymbolAddress((void**)&cnt_g, g_cnt_g);
    cudaGetSymbolAddress((void**)&off_g, g_off_g);
    cudaGetSymbolAddress((void**)&off_p, g_off_p);
    cudaGetSymbolAddress((void**)&cur_g, g_cur_g);
    cudaGetSymbolAddress((void**)&cur_p, g_cur_p);
    cudaGetSymbolAddress((void**)&csr_pg, g_csr_pg);
    cudaGetSymbolAddress((void**)&csr_gp, g_csr_gp);
    cudaGetSymbolAddress((void**)&bsum_g, g_bsum_g);
    cudaGetSymbolAddress((void**)&bsum_p, g_bsum_p);

    float* xp[2] = { xp_buf, xp_buf + (ll)NP_MAX * DD };
    float* xg[2] = { xg_buf, xg_buf + (ll)NG_MAX * DD };

    const int TB = 256;
    const int AGG_SMEM = 32 * 1024 + 64 * 1024;   // sW + sAX
    cudaFuncSetAttribute(agg_update_kernel,
                         cudaFuncAttributeMaxDynamicSharedMemorySize, AGG_SMEM);

    // ---- CSR build (reused by all layers) ----
    zero2_kernel<<<cdiv(NG + NP, TB), TB>>>(cnt_g, NG, cnt_p, NP);
    hist2_kernel<<<cdiv(2LL * E, TB), TB>>>(dst_pg, cnt_g, dst_gp, cnt_p, E);

    int nbg = cdiv(NG, 4096), nbp = cdiv(NP, 4096);
    scan_reduce_kernel<<<nbg, 512>>>(cnt_g, bsum_g, NG);
    scan_reduce_kernel<<<nbp, 512>>>(cnt_p, bsum_p, NP);
    scan_bsum_kernel<<<1, 32>>>(bsum_g, nbg, &off_g[NG]);
    scan_bsum_kernel<<<1, 32>>>(bsum_p, nbp, &off_p[NP]);
    scan_apply_kernel<<<nbg, 512>>>(cnt_g, bsum_g, off_g, cur_g, NG);
    scan_apply_kernel<<<nbp, 512>>>(cnt_p, bsum_p, off_p, cur_p, NP);

    fill2_kernel<<<cdiv(2LL * E, TB), TB>>>(src_pg, dst_pg, cur_g, csr_pg,
                                            src_gp, dst_gp, cur_p, csr_gp, E);

    // ---- input embeddings ----
    init_xp_kernel<<<cdiv((ll)NP * 16, TB), TB>>>(protein_emb, protein_nid, xp[0], NP);
    gemm_xg_kernel<<<cdiv(NG, 64), 256>>>(go_x, lin_W, lin_b, go_emb, go_nid, xg[0], NG, K);

    // ---- layers ----
    int cur = 0;
    for (int l = 0; l < L; l++) {
        int nxt = cur ^ 1;
        int relu = (l < L - 1) ? 1 : 0;
        agg_update_kernel<<<370, 512, AGG_SMEM>>>(xp[cur], xg[cur], off_g, csr_pg,
                                        Wl + (ll)(l * 2 + 0) * 64 * 64,
                                        bl + (ll)(l * 2 + 0) * 64,
                                        Wr + (ll)(l * 2 + 0) * 64 * 64,
                                        xg[nxt], NG, relu);
        agg_update_kernel<<<370, 512, AGG_SMEM>>>(xg[cur], xp[cur], off_p, csr_gp,
                                        Wl + (ll)(l * 2 + 1) * 64 * 64,
                                        bl + (ll)(l * 2 + 1) * 64,
                                        Wr + (ll)(l * 2 + 1) * 64 * 64,
                                        xp[nxt], NP, relu);
        cur = nxt;
    }

    classify_kernel<<<cdiv((ll)EL * 8, TB), TB>>>(xp[cur], xg[cur],
                                                  label_src, label_dst,
                                                  (float*)d_out, EL);
}

// round 9
// speedup vs baseline: 2.7942x; 1.1657x over previous
#include <cuda_runtime.h>
#include <cstdint>

typedef unsigned long long ull;
typedef long long ll;

// Problem constants (GB300 bench shapes)
#define DD     64
#define NP_MAX 100000
#define NG_MAX 40000
#define E_MAX  1600000
#define RPW    4            // rows per warp-group unit in fused update

// ---------------- static scratch (no runtime allocation allowed) -------------
__device__ float g_xp[2][NP_MAX * DD];
__device__ float g_xg[2][NG_MAX * DD];
__device__ int   g_cnt_p[NP_MAX];
__device__ int   g_cnt_g[NG_MAX];
__device__ int   g_off_g[NG_MAX + 1];
__device__ int   g_off_p[NP_MAX + 1];
__device__ int   g_cur_g[NG_MAX];
__device__ int   g_cur_p[NP_MAX];
__device__ int   g_csr_pg[E_MAX];
__device__ int   g_csr_gp[E_MAX];
__device__ int   g_bsum_g[64];
__device__ int   g_bsum_p[64];
__device__ int   g_wctr[8];          // work-steal counters: [layer][side]

// ---------------- f32x2 helpers (sm_103a packed FMA only via PTX) -------------
__device__ __forceinline__ ull pack2(float lo, float hi) {
    ull r; asm("mov.b64 %0, {%1, %2};" : "=l"(r) : "f"(lo), "f"(hi)); return r;
}
__device__ __forceinline__ void unpack2(ull v, float& lo, float& hi) {
    asm("mov.b64 {%0, %1}, %2;" : "=f"(lo), "=f"(hi) : "l"(v));
}
__device__ __forceinline__ void ffma2(ull& d, ull a, ull b) {   // d = a*b + d (2x fp32)
    asm("fma.rn.f32x2 %0, %1, %2, %0;" : "+l"(d) : "l"(a), "l"(b));
}
__device__ __forceinline__ void fadd2(ull& d, ull a) {          // d += a
    asm("add.rn.f32x2 %0, %0, %1;" : "+l"(d) : "l"(a));
}
__device__ __forceinline__ void fmul2(ull& d, ull a) {          // d *= a
    asm("mul.rn.f32x2 %0, %0, %1;" : "+l"(d) : "l"(a));
}

// ---------------- small utility kernels --------------------------------------
__global__ void zero2_kernel(int* a, int na, int* b, int nb, int* wctr) {
    int i = blockIdx.x * blockDim.x + threadIdx.x;
    if (i < 8) wctr[i] = 0;
    if (i < na) a[i] = 0;
    else if (i - na < nb) b[i - na] = 0;
}

// both histograms in one launch
__global__ void hist2_kernel(const int* __restrict__ d0, int* __restrict__ c0,
                             const int* __restrict__ d1, int* __restrict__ c1, int E) {
    int i = blockIdx.x * blockDim.x + threadIdx.x;
    if (i < E) atomicAdd(&c0[d0[i]], 1);
    else if (i < 2 * E) atomicAdd(&c1[d1[i - E]], 1);
}

// ---------------- multi-block exclusive scan (3 phases) ----------------------
__global__ void scan_reduce_kernel(const int* __restrict__ cnt, int* __restrict__ bsum, int n) {
    __shared__ int ws[16];
    int base = blockIdx.x * 4096;
    int s = 0;
    for (int i = threadIdx.x; i < 4096; i += 512) {
        int j = base + i;
        if (j < n) s += cnt[j];
    }
#pragma unroll
    for (int o = 16; o; o >>= 1) s += __shfl_down_sync(0xffffffffu, s, o);
    if ((threadIdx.x & 31) == 0) ws[threadIdx.x >> 5] = s;
    __syncthreads();
    if (threadIdx.x < 16) {
        s = ws[threadIdx.x];
#pragma unroll
        for (int o = 8; o; o >>= 1) s += __shfl_down_sync(0xffffu, s, o);
        if (threadIdx.x == 0) bsum[blockIdx.x] = s;
    }
}

__global__ void scan_bsum_kernel(int* __restrict__ bsum, int nb, int* __restrict__ off_n) {
    int tid = threadIdx.x;
    int v = (tid < nb) ? bsum[tid] : 0;
    int x = v;
#pragma unroll
    for (int o = 1; o < 32; o <<= 1) {
        int y = __shfl_up_sync(0xffffffffu, x, o);
        if (tid >= o) x += y;
    }
    if (tid < nb) bsum[tid] = x - v;
    if (tid == 31) *off_n = x;
}

__global__ void scan_apply_kernel(const int* __restrict__ cnt, const int* __restrict__ bsum,
                                  int* __restrict__ off, int* __restrict__ cursor, int n) {
    __shared__ int ws[16];
    int base = blockIdx.x * 4096 + threadIdx.x * 8;
    int v[8]; int t = 0;
#pragma unroll
    for (int j = 0; j < 8; j++) {
        int i = base + j;
        v[j] = (i < n) ? cnt[i] : 0;
        t += v[j];
    }
    int lane = threadIdx.x & 31, warp = threadIdx.x >> 5;
    int x = t;
#pragma unroll
    for (int o = 1; o < 32; o <<= 1) {
        int y = __shfl_up_sync(0xffffffffu, x, o);
        if (lane >= o) x += y;
    }
    if (lane == 31) ws[warp] = x;
    __syncthreads();
    if (warp == 0 && lane < 16) {
        int w = ws[lane];
#pragma unroll
        for (int o = 1; o < 16; o <<= 1) {
            int y = __shfl_up_sync(0xffffu, w, o);
            if (lane >= o) w += y;
        }
        ws[lane] = w;
    }
    __syncthreads();
    int run = x - t + (warp ? ws[warp - 1] : 0) + bsum[blockIdx.x];
#pragma unroll
    for (int j = 0; j < 8; j++) {
        int i = base + j;
        if (i < n) { off[i] = run; cursor[i] = run; }
        run += v[j];
    }
}

// both CSR fills in one launch
__global__ void fill2_kernel(const int* __restrict__ s0, const int* __restrict__ d0,
                             int* __restrict__ cu0, int* __restrict__ cs0,
                             const int* __restrict__ s1, const int* __restrict__ d1,
                             int* __restrict__ cu1, int* __restrict__ cs1, int E) {
    int i = blockIdx.x * blockDim.x + threadIdx.x;
    if (i < E) {
        int pos = atomicAdd(&cu0[d0[i]], 1);
        cs0[pos] = s0[i];
    } else if (i < 2 * E) {
        int j = i - E;
        int pos = atomicAdd(&cu1[d1[j]], 1);
        cs1[pos] = s1[j];
    }
}

// xp0[i,:] = protein_emb[nid[i],:]  (float4 vectorized)
__global__ void init_xp_kernel(const float* __restrict__ pe, const int* __restrict__ nid,
                               float* __restrict__ out, int np) {
    long long idx = (long long)blockIdx.x * blockDim.x + threadIdx.x;
    long long n = (long long)np * 16;
    if (idx >= n) return;
    int r = (int)(idx >> 4);
    int j = (int)(idx & 15);
    const float4* src = (const float4*)(pe + (ll)nid[r] * DD);
    ((float4*)(out + (ll)r * DD))[j] = __ldg(src + j);
}

// ---------------- xg init GEMM: [M,K] @ [K,64] + bias + emb[nid] -------------
#define GBK 8
__global__ void gemm_xg_kernel(const float* __restrict__ A, const float* __restrict__ W,
                               const float* __restrict__ bias, const float* __restrict__ emb,
                               const int* __restrict__ nid, float* __restrict__ out,
                               int M, int K) {
    __shared__ float As[GBK][68];
    __shared__ __align__(16) float sB[GBK][32][2];
    int tid = threadIdx.x;          // 256 threads
    int tx = tid & 15;
    int ty = tid >> 4;
    int rowBase = blockIdx.x * 64;

    ull acc[4][2];
#pragma unroll
    for (int i = 0; i < 4; i++) { acc[i][0] = 0ull; acc[i][1] = 0ull; }

    int la_row = tid >> 2;
    int la_k   = (tid & 3) * 2;
    int lb_k   = tid >> 5;
    int lb_c   = (tid & 31) * 2;

    const float* Arow = A + (ll)(rowBase + la_row) * K;
    bool a_ok = (rowBase + la_row) < M;

    for (int k0 = 0; k0 < K; k0 += GBK) {
        float a0 = 0.f, a1 = 0.f;
        if (a_ok) { a0 = Arow[k0 + la_k]; a1 = Arow[k0 + la_k + 1]; }
        As[la_k][la_row] = a0;
        As[la_k + 1][la_row] = a1;
        {
            float w0 = W[(ll)(k0 + lb_k) * 64 + lb_c];
            float w1 = W[(ll)(k0 + lb_k) * 64 + lb_c + 1];
            sB[lb_k][lb_c & 31][lb_c >> 5]       = w0;
            sB[lb_k][(lb_c + 1) & 31][(lb_c + 1) >> 5] = w1;
        }
        __syncthreads();
#pragma unroll
        for (int k = 0; k < GBK; k++) {
            float4 av = *(const float4*)&As[k][ty * 4];
            longlong2 bv = *(const longlong2*)&sB[k][2 * tx][0];
            ull b0 = (ull)bv.x, b1 = (ull)bv.y;
            ull p0 = pack2(av.x, av.x);
            ull p1 = pack2(av.y, av.y);
            ull p2 = pack2(av.z, av.z);
            ull p3 = pack2(av.w, av.w);
            ffma2(acc[0][0], p0, b0); ffma2(acc[0][1], p0, b1);
            ffma2(acc[1][0], p1, b0); ffma2(acc[1][1], p1, b1);
            ffma2(acc[2][0], p2, b0); ffma2(acc[2][1], p2, b1);
            ffma2(acc[3][0], p3, b0); ffma2(acc[3][1], p3, b1);
        }
        __syncthreads();
    }

#pragma unroll
    for (int i = 0; i < 4; i++) {
        int r = rowBase + ty * 4 + i;
        if (r >= M) continue;
        int g = nid[r];
#pragma unroll
        for (int j = 0; j < 2; j++) {
            float lo, hi; unpack2(acc[i][j], lo, hi);
            int cl = 2 * tx + j, ch = 2 * tx + j + 32;
            out[(ll)r * 64 + cl] = lo + bias[cl] + emb[(ll)g * 64 + cl];
            out[(ll)r * 64 + ch] = hi + bias[ch] + emb[(ll)g * 64 + ch];
        }
    }
}

// --------- fused layer kernel: BOTH sides in one launch, work-stealing -------
// Blocks [0, gb_go) do go-side (gather xp -> update xg), rest do protein side.
// Warp grabs 4-row groups from a per-side global counter (balanced tails).
// Dynamic smem: sW 32KB (this side's packed Wl/Wr) + sAX 64KB staging.
__global__ void __launch_bounds__(512, 2) layer_kernel(
    const float* __restrict__ xp_in, const float* __restrict__ xg_in,
    float* __restrict__ xg_out, float* __restrict__ xp_out,
    const int* __restrict__ off_g, const int* __restrict__ csr_pg,
    const int* __restrict__ off_p, const int* __restrict__ csr_gp,
    const float* __restrict__ Wl6, const float* __restrict__ bl6,
    const float* __restrict__ Wr6, int l,
    int NG, int NP, int do_relu, int* __restrict__ wctr, int gb_go) {
    extern __shared__ __align__(16) float smem_dyn[];
    float* sW = smem_dyn;                       // 8192 floats = 32KB
    ull*   sAX = (ull*)(smem_dyn + 8192);       // 8192 ull = 64KB

    bool is_go = (blockIdx.x < gb_go);
    const float* xsrc = is_go ? xp_in : xg_in;
    const float* xdst = is_go ? xg_in : xp_in;
    float*       out  = is_go ? xg_out : xp_out;
    const int*   off  = is_go ? off_g : off_p;
    const int*   csr  = is_go ? csr_pg : csr_gp;
    int          n    = is_go ? NG : NP;
    int side = is_go ? 0 : 1;
    const float* Wl = Wl6 + (ll)(l * 2 + side) * 4096;
    const float* Wr = Wr6 + (ll)(l * 2 + side) * 4096;
    const float* bl = bl6 + (ll)(l * 2 + side) * 64;
    int* myctr = wctr + l * 2 + side;

    // sW[(k*32+pair)*4 + {0,1,2,3}] = {Wl[k][2p], Wl[k][2p+1], Wr[k][2p], Wr[k][2p+1]}
    for (int idx = threadIdx.x; idx < 4096; idx += blockDim.x) {
        int k = idx >> 6, c = idx & 63;
        float* d = &sW[(k * 32 + (c >> 1)) * 4];
        d[c & 1]       = Wl[idx];
        d[2 + (c & 1)] = Wr[idx];
    }
    __syncthreads();

    int warp = threadIdx.x >> 5;
    int lane = threadIdx.x & 31;
    int ngroups = (n + RPW - 1) / RPW;

    ull* myAX = sAX + warp * (RPW * 64 * 2);    // 512 ull per warp

    float bl_lo = __ldg(&bl[2 * lane]);
    float bl_hi = __ldg(&bl[2 * lane + 1]);
    ull binit = pack2(bl_lo, bl_hi);

    for (;;) {
        int g;
        if (lane == 0) g = atomicAdd(myctr, 1);
        g = __shfl_sync(0xffffffffu, g, 0);
        if (g >= ngroups) break;
        int row0 = g * RPW;
        float2 af[RPW], xf[RPW];

        // ---- gather + mean for RPW rows (unroll 8 for MLP) ----
#pragma unroll
        for (int r = 0; r < RPW; r++) {
            int row = row0 + r;
            ull aa0 = 0ull, aa1 = 0ull;
            float2 xx = make_float2(0.f, 0.f);
            float ic = 0.f;
            if (row < n) {
                int e0 = __ldg(&off[row]);
                int e1 = __ldg(&off[row + 1]);
                int e = e0;
                for (; e + 8 <= e1; e += 8) {
                    int s0 = __ldg(&csr[e]);
                    int s1 = __ldg(&csr[e + 1]);
                    int s2 = __ldg(&csr[e + 2]);
                    int s3 = __ldg(&csr[e + 3]);
                    int s4 = __ldg(&csr[e + 4]);
                    int s5 = __ldg(&csr[e + 5]);
                    int s6 = __ldg(&csr[e + 6]);
                    int s7 = __ldg(&csr[e + 7]);
                    ull v0 = __ldg((const ull*)(xsrc + (ll)s0 * DD) + lane);
                    ull v1 = __ldg((const ull*)(xsrc + (ll)s1 * DD) + lane);
                    ull v2 = __ldg((const ull*)(xsrc + (ll)s2 * DD) + lane);
                    ull v3 = __ldg((const ull*)(xsrc + (ll)s3 * DD) + lane);
                    ull v4 = __ldg((const ull*)(xsrc + (ll)s4 * DD) + lane);
                    ull v5 = __ldg((const ull*)(xsrc + (ll)s5 * DD) + lane);
                    ull v6 = __ldg((const ull*)(xsrc + (ll)s6 * DD) + lane);
                    ull v7 = __ldg((const ull*)(xsrc + (ll)s7 * DD) + lane);
                    fadd2(aa0, v0); fadd2(aa1, v1); fadd2(aa0, v2); fadd2(aa1, v3);
                    fadd2(aa0, v4); fadd2(aa1, v5); fadd2(aa0, v6); fadd2(aa1, v7);
                }
                for (; e < e1; e++) {
                    int s = __ldg(&csr[e]);
                    fadd2(aa0, __ldg((const ull*)(xsrc + (ll)s * DD) + lane));
                }
                ic = 1.0f / (float)max(e1 - e0, 1);
                xx = __ldg((const float2*)(xdst + (ll)row * DD) + lane);
            }
            fadd2(aa0, aa1);
            fmul2(aa0, pack2(ic, ic));
            unpack2(aa0, af[r].x, af[r].y);
            xf[r] = xx;
        }

        // ---- stage duplicated operands to smem: lane l owns k=2l, 2l+1 ----
        __syncwarp();
#pragma unroll
        for (int r = 0; r < RPW; r++) {
            ulonglong2 s0, s1;
            s0.x = pack2(af[r].x, af[r].x); s0.y = pack2(xf[r].x, xf[r].x);
            s1.x = pack2(af[r].y, af[r].y); s1.y = pack2(xf[r].y, xf[r].y);
            *(ulonglong2*)&myAX[(r * 64 + 2 * lane) * 2]     = s0;
            *(ulonglong2*)&myAX[(r * 64 + 2 * lane + 1) * 2] = s1;
        }
        __syncwarp();

        // ---- matvec: acc = a @ Wl + x @ Wr (+ bias), smem broadcast ----
        ull acc[RPW];
#pragma unroll
        for (int r = 0; r < RPW; r++) acc[r] = binit;

#pragma unroll 4
        for (int k = 0; k < 64; k++) {
            longlong2 wv = *(const longlong2*)&sW[(k * 32 + lane) * 4];
            ull wl2 = (ull)wv.x, wr2 = (ull)wv.y;
#pragma unroll
            for (int r = 0; r < RPW; r++) {
                ulonglong2 ax = *(const ulonglong2*)&myAX[(r * 64 + k) * 2];
                ffma2(acc[r], (ull)ax.x, wl2);
                ffma2(acc[r], (ull)ax.y, wr2);
            }
        }

#pragma unroll
        for (int r = 0; r < RPW; r++) {
            int row = row0 + r;
            if (row < n) {
                float lo, hi; unpack2(acc[r], lo, hi);
                if (do_relu) { lo = fmaxf(lo, 0.0f); hi = fmaxf(hi, 0.0f); }
                float2 o; o.x = lo; o.y = hi;
                *((float2*)(out + (ll)row * DD) + lane) = o;
            }
        }
    }
}

// ---------------- classifier: out[e] = dot(xp[ls[e]], xg[ld[e]]) (8 thr/edge)
__global__ void classify_kernel(const float* __restrict__ xp, const float* __restrict__ xg,
                                const int* __restrict__ ls, const int* __restrict__ ld,
                                float* __restrict__ out, int E) {
    long long idx = (long long)blockIdx.x * blockDim.x + threadIdx.x;
    long long total = (long long)E * 8;
    if (idx >= total) return;
    int e = (int)(idx >> 3);
    int j = (int)(idx & 7);
    int a = __ldg(&ls[e]);
    int b = __ldg(&ld[e]);
    const float4* pa = (const float4*)(xp + (ll)a * DD);
    const float4* pb = (const float4*)(xg + (ll)b * DD);
    float4 u0 = __ldg(pa + j * 2);
    float4 u1 = __ldg(pa + j * 2 + 1);
    float4 v0 = __ldg(pb + j * 2);
    float4 v1 = __ldg(pb + j * 2 + 1);
    float s = u0.x * v0.x + u0.y * v0.y + u0.z * v0.z + u0.w * v0.w
            + u1.x * v1.x + u1.y * v1.y + u1.z * v1.z + u1.w * v1.w;
    s += __shfl_xor_sync(0xffffffffu, s, 4);
    s += __shfl_xor_sync(0xffffffffu, s, 2);
    s += __shfl_xor_sync(0xffffffffu, s, 1);
    if (j == 0) out[e] = s;
}

// ---------------- host driver ------------------------------------------------
static inline int cdiv(long long a, int b) { return (int)((a + b - 1) / b); }

extern "C" void kernel_launch(void* const* d_in, const int* in_sizes, int n_in,
                              void* d_out, int out_size) {
    const float* go_x        = (const float*)d_in[0];
    const float* protein_emb = (const float*)d_in[1];
    const float* go_emb      = (const float*)d_in[2];
    const float* lin_W       = (const float*)d_in[3];
    const float* lin_b       = (const float*)d_in[4];
    const float* Wl          = (const float*)d_in[5];
    const float* bl          = (const float*)d_in[6];
    const float* Wr          = (const float*)d_in[7];
    const int*   protein_nid = (const int*)d_in[8];
    const int*   go_nid      = (const int*)d_in[9];
    const int*   src_pg      = (const int*)d_in[10];
    const int*   dst_pg      = (const int*)d_in[11];
    const int*   src_gp      = (const int*)d_in[12];
    const int*   dst_gp      = (const int*)d_in[13];
    const int*   label_src   = (const int*)d_in[14];
    const int*   label_dst   = (const int*)d_in[15];

    int NP = in_sizes[8];
    int NG = in_sizes[9];
    int E  = in_sizes[10];
    int EL = in_sizes[14];
    int K  = (int)((long long)in_sizes[0] / NG);
    int L  = (int)((long long)in_sizes[5] / (2 * 64 * 64));

    float *xp_buf, *xg_buf;
    int *cnt_p, *cnt_g, *off_g, *off_p, *cur_g, *cur_p, *csr_pg, *csr_gp;
    int *bsum_g, *bsum_p, *wctr;
    cudaGetSymbolAddress((void**)&xp_buf, g_xp);
    cudaGetSymbolAddress((void**)&xg_buf, g_xg);
    cudaGetSymbolAddress((void**)&cnt_p, g_cnt_p);
    cudaGetSymbolAddress((void**)&cnt_g, g_cnt_g);
    cudaGetSymbolAddress((void**)&off_g, g_off_g);
    cudaGetSymbolAddress((void**)&off_p, g_off_p);
    cudaGetSymbolAddress((void**)&cur_g, g_cur_g);
    cudaGetSymbolAddress((void**)&cur_p, g_cur_p);
    cudaGetSymbolAddress((void**)&csr_pg, g_csr_pg);
    cudaGetSymbolAddress((void**)&csr_gp, g_csr_gp);
    cudaGetSymbolAddress((void**)&bsum_g, g_bsum_g);
    cudaGetSymbolAddress((void**)&bsum_p, g_bsum_p);
    cudaGetSymbolAddress((void**)&wctr, g_wctr);

    float* xp[2] = { xp_buf, xp_buf + (ll)NP_MAX * DD };
    float* xg[2] = { xg_buf, xg_buf + (ll)NG_MAX * DD };

    const int TB = 256;
    const int AGG_SMEM = 32 * 1024 + 64 * 1024;   // sW + sAX
    cudaFuncSetAttribute(layer_kernel,
                         cudaFuncAttributeMaxDynamicSharedMemorySize, AGG_SMEM);

    // ---- CSR build (reused by all layers) ----
    zero2_kernel<<<cdiv(NG + NP, TB), TB>>>(cnt_g, NG, cnt_p, NP, wctr);
    hist2_kernel<<<cdiv(2LL * E, TB), TB>>>(dst_pg, cnt_g, dst_gp, cnt_p, E);

    int nbg = cdiv(NG, 4096), nbp = cdiv(NP, 4096);
    scan_reduce_kernel<<<nbg, 512>>>(cnt_g, bsum_g, NG);
    scan_reduce_kernel<<<nbp, 512>>>(cnt_p, bsum_p, NP);
    scan_bsum_kernel<<<1, 32>>>(bsum_g, nbg, &off_g[NG]);
    scan_bsum_kernel<<<1, 32>>>(bsum_p, nbp, &off_p[NP]);
    scan_apply_kernel<<<nbg, 512>>>(cnt_g, bsum_g, off_g, cur_g, NG);
    scan_apply_kernel<<<nbp, 512>>>(cnt_p, bsum_p, off_p, cur_p, NP);

    fill2_kernel<<<cdiv(2LL * E, TB), TB>>>(src_pg, dst_pg, cur_g, csr_pg,
                                            src_gp, dst_gp, cur_p, csr_gp, E);

    // ---- input embeddings ----
    init_xp_kernel<<<cdiv((ll)NP * 16, TB), TB>>>(protein_emb, protein_nid, xp[0], NP);
    gemm_xg_kernel<<<cdiv(NG, 64), 256>>>(go_x, lin_W, lin_b, go_emb, go_nid, xg[0], NG, K);

    // ---- layers: one combined launch per layer (go + protein concurrent) ----
    const int GB_GO = 128, GB_P = 168;            // 296 blocks = 2/SM
    int cur = 0;
    for (int l = 0; l < L; l++) {
        int nxt = cur ^ 1;
        int relu = (l < L - 1) ? 1 : 0;
        layer_kernel<<<GB_GO + GB_P, 512, AGG_SMEM>>>(
            xp[cur], xg[cur], xg[nxt], xp[nxt],
            off_g, csr_pg, off_p, csr_gp,
            Wl, bl, Wr, l, NG, NP, relu, wctr, GB_GO);
        cur = nxt;
    }

    classify_kernel<<<cdiv((ll)EL * 8, TB), TB>>>(xp[cur], xg[cur],
                                                  label_src, label_dst,
                                                  (float*)d_out, EL);
}